// round 15
// baseline (speedup 1.0000x reference)
#include <cuda_runtime.h>
#include <cuda_fp16.h>
#include <cstdint>

#define S_TOK 8192
#define MDIM  1024
#define EEXP  8
#define HDIM  2048
#define CCAP  2048
#define BB    4
#define TT    2048

// ---------------- scratch (device globals; no allocations allowed) ----------
__device__ int   g_e0[S_TOK], g_e1[S_TOK];
__device__ float g_g0[S_TOK], g_g1[S_TOK];
__device__ int   g_pos0[S_TOK], g_pos1[S_TOK];
__device__ int   g_tok[EEXP * CCAP];
__device__ int   g_ne[EEXP];
__device__ float g_w2sum[EEXP * HDIM];
__device__ float g_b2sum[EEXP];
__device__ float g_z[EEXP * CCAP];
// fp16 operands (single-term, 11-bit mantissa)
__device__ __half g_xh[S_TOK * MDIM];
__device__ __half g_w1h[EEXP * MDIM * HDIM];   // native layout [e][m][h]

// ---------------- PTX helpers (family-portable only) -------------------------
__device__ __forceinline__ uint32_t smem_u32(const void* p) {
    uint32_t a;
    asm("{ .reg .u64 t; cvta.to.shared.u64 t, %1; cvt.u32.u64 %0, t; }" : "=r"(a) : "l"(p));
    return a;
}
__device__ __forceinline__ void ldsm4(uint32_t* r, uint32_t addr) {
    asm volatile("ldmatrix.sync.aligned.m8n8.x4.shared.b16 {%0,%1,%2,%3}, [%4];"
                 : "=r"(r[0]), "=r"(r[1]), "=r"(r[2]), "=r"(r[3]) : "r"(addr));
}
__device__ __forceinline__ void ldsm4t(uint32_t* r, uint32_t addr) {
    asm volatile("ldmatrix.sync.aligned.m8n8.x4.trans.shared.b16 {%0,%1,%2,%3}, [%4];"
                 : "=r"(r[0]), "=r"(r[1]), "=r"(r[2]), "=r"(r[3]) : "r"(addr));
}
__device__ __forceinline__ void mma16816(float* c, const uint32_t* a, const uint32_t* b) {
    asm volatile("mma.sync.aligned.m16n8k16.row.col.f32.f16.f16.f32 "
                 "{%0,%1,%2,%3}, {%4,%5,%6,%7}, {%8,%9}, {%0,%1,%2,%3};"
                 : "+f"(c[0]), "+f"(c[1]), "+f"(c[2]), "+f"(c[3])
                 : "r"(a[0]), "r"(a[1]), "r"(a[2]), "r"(a[3]), "r"(b[0]), "r"(b[1]));
}
#define CP_ASYNC16(dst, src, sz) \
    asm volatile("cp.async.cg.shared.global [%0], [%1], 16, %2;" :: "r"(dst), "l"(src), "r"(sz) : "memory")
#define CP_COMMIT() asm volatile("cp.async.commit_group;" ::: "memory")
#define CP_WAIT2()  asm volatile("cp.async.wait_group 2;" ::: "memory")

// ---------------- main chain: routing + w2 row-sum + b2 row-sum --------------
// blocks [0,1024): routing (warp per token + x->fp16)
// blocks [1024,3072): w2 row-sum
// block  3072: b2 row-sum
__global__ __launch_bounds__(256) void route_w2_kernel(const float* __restrict__ x,
                                                       const float* __restrict__ wg,
                                                       const float* __restrict__ w2,
                                                       const float* __restrict__ b2) {
    int bx = blockIdx.x;
    int lane = threadIdx.x & 31;
    if (bx < 1024) {
        // ---- routing ----
        int gwarp = (bx * 256 + threadIdx.x) >> 5;
        const float* xr = x + (size_t)gwarp * MDIM;
        __half* xo = g_xh + (size_t)gwarp * MDIM;
        float acc[8];
#pragma unroll
        for (int e = 0; e < 8; e++) acc[e] = 0.f;
        for (int k = lane; k < MDIM; k += 32) {
            float xv = xr[k];
            xo[k] = __float2half(xv);
            const float4* w4 = (const float4*)(wg + (size_t)k * EEXP);
            float4 a = w4[0], b = w4[1];
            acc[0] += xv * a.x; acc[1] += xv * a.y; acc[2] += xv * a.z; acc[3] += xv * a.w;
            acc[4] += xv * b.x; acc[5] += xv * b.y; acc[6] += xv * b.z; acc[7] += xv * b.w;
        }
#pragma unroll
        for (int e = 0; e < 8; e++) {
#pragma unroll
            for (int o = 16; o; o >>= 1) acc[e] += __shfl_xor_sync(0xffffffffu, acc[e], o);
        }
        if (lane == 0) {
            float mx = acc[0];
#pragma unroll
            for (int e = 1; e < 8; e++) mx = fmaxf(mx, acc[e]);
            float p[8]; float den = 0.f;
#pragma unroll
            for (int e = 0; e < 8; e++) { p[e] = expf(acc[e] - mx); den += p[e]; }
#pragma unroll
            for (int e = 0; e < 8; e++) p[e] /= den;
            int i0 = 0; float v0 = p[0];
#pragma unroll
            for (int e = 1; e < 8; e++) if (p[e] > v0) { v0 = p[e]; i0 = e; }
            int i1 = -1; float v1 = -1.f;
#pragma unroll
            for (int e = 0; e < 8; e++) if (e != i0 && p[e] > v1) { v1 = p[e]; i1 = e; }
            float gden = v0 + v1 + 1e-9f;
            g_e0[gwarp] = i0;  g_e1[gwarp] = i1;
            g_g0[gwarp] = v0 / gden;  g_g1[gwarp] = v1 / gden;
        }
        return;
    }
    if (bx < 3072) {
        // ---- w2 row-sum ----
        int row = ((bx - 1024) * 256 + threadIdx.x) >> 5;
        const float4* p = (const float4*)(w2 + (size_t)row * MDIM);
        float s = 0.f;
#pragma unroll
        for (int i = 0; i < 8; i++) {
            float4 v = p[lane + i * 32];
            s += (v.x + v.y) + (v.z + v.w);
        }
#pragma unroll
        for (int o = 16; o; o >>= 1) s += __shfl_xor_sync(0xffffffffu, s, o);
        if (lane == 0) g_w2sum[row] = s;
        return;
    }
    // ---- b2 row-sum ----
    int warp = threadIdx.x >> 5;
    if (warp < EEXP) {
        float s = 0.f;
        for (int m = lane; m < MDIM; m += 32) s += b2[warp * MDIM + m];
#pragma unroll
        for (int o = 16; o; o >>= 1) s += __shfl_xor_sync(0xffffffffu, s, o);
        if (lane == 0) g_b2sum[warp] = s;
    }
}

// ---------------- side chain: w1 -> fp16 (overlaps with routing+scan) -------
__global__ __launch_bounds__(256) void cvt_w1_kernel(const float* __restrict__ w1) {
    int i = blockIdx.x * 256 + threadIdx.x;
    float4 v = ((const float4*)w1)[i];
    __half2* o = (__half2*)g_w1h;
    o[2*i]   = __floats2half2_rn(v.x, v.y);
    o[2*i+1] = __floats2half2_rn(v.z, v.w);
}

// ---------------- ordered rank / capacity scan: single pass prefix ----------
__global__ __launch_bounds__(1024) void scan_kernel() {
    __shared__ unsigned long long wtot[32][4];
    __shared__ unsigned long long wbase[32][4];
    __shared__ unsigned long long gtot[4];
    int tid = threadIdx.x, lane = tid & 31, warp = tid >> 5;

    int e0v[8], e1v[8];
    unsigned long long c[4] = {0ull, 0ull, 0ull, 0ull};
#pragma unroll
    for (int i = 0; i < 8; i++) {
        int s = tid * 8 + i;
        int e0 = g_e0[s], e1 = g_e1[s];
        e0v[i] = e0; e1v[i] = e1;
        if (e0 < 4) c[0] += 1ull << (e0 * 16); else c[1] += 1ull << ((e0 - 4) * 16);
        if (e1 < 4) c[2] += 1ull << (e1 * 16); else c[3] += 1ull << ((e1 - 4) * 16);
    }
    unsigned long long inc[4] = {c[0], c[1], c[2], c[3]};
#pragma unroll
    for (int st = 1; st < 32; st <<= 1) {
#pragma unroll
        for (int q = 0; q < 4; q++) {
            unsigned long long o = __shfl_up_sync(0xffffffffu, inc[q], st);
            if (lane >= st) inc[q] += o;
        }
    }
    if (lane == 31) {
#pragma unroll
        for (int q = 0; q < 4; q++) wtot[warp][q] = inc[q];
    }
    __syncthreads();
    if (warp == 0) {
        unsigned long long t[4], ti[4];
#pragma unroll
        for (int q = 0; q < 4; q++) { t[q] = wtot[lane][q]; ti[q] = t[q]; }
#pragma unroll
        for (int st = 1; st < 32; st <<= 1) {
#pragma unroll
            for (int q = 0; q < 4; q++) {
                unsigned long long o = __shfl_up_sync(0xffffffffu, ti[q], st);
                if (lane >= st) ti[q] += o;
            }
        }
#pragma unroll
        for (int q = 0; q < 4; q++) wbase[lane][q] = ti[q] - t[q];
        if (lane == 31) {
#pragma unroll
            for (int q = 0; q < 4; q++) gtot[q] = ti[q];
        }
    }
    __syncthreads();

    int base[16];
#pragma unroll
    for (int cat = 0; cat < 16; cat++) {
        int q = cat >> 2, r = cat & 3;
        unsigned long long el = inc[q] - c[q];
        int b = (int)((wbase[warp][q] >> (r * 16)) & 0xffff)
              + (int)((el >> (r * 16)) & 0xffff);
        if (cat >= 8) b += (int)((gtot[q - 2] >> (r * 16)) & 0xffff);
        base[cat] = b;
    }
#pragma unroll
    for (int i = 0; i < 8; i++) {
        int s = tid * 8 + i;
        int p0 = base[e0v[i]]++;
        if (p0 < CCAP) { g_pos0[s] = p0; g_tok[e0v[i] * CCAP + p0] = s; } else g_pos0[s] = -1;
        int p1 = base[8 + e1v[i]]++;
        if (p1 < CCAP) { g_pos1[s] = p1; g_tok[e1v[i] * CCAP + p1] = s; } else g_pos1[s] = -1;
    }
    // fused: zero z accumulators + expert counts
#pragma unroll
    for (int i = 0; i < EEXP * CCAP / 1024; i++) g_z[tid + i * 1024] = 0.f;
    if (tid < EEXP) {
        int q = tid >> 2, r = tid & 3;
        int tot = (int)((gtot[q] >> (r * 16)) & 0xffff) + (int)((gtot[q + 2] >> (r * 16)) & 0xffff);
        g_ne[tid] = min(tot, CCAP);
    }
}

// ---------------- FFN via mma.sync fp16 (single term) ------------------------
// CTA tile: 128 tok x 128 H, BK = 32, 4-stage cp.async pipeline, 2 CTAs/SM.
// One __syncthreads per chunk; next tile's loads issued BEFORE compute so
// cp.async overlaps the MMAs. (Exact config of the 268.6/260.8 us runs — FROZEN.)
#define BKC      32
#define NCH      (MDIM / BKC)        // 32
#define AROWB    80
#define BROWB    272
#define A_SZ     (128 * AROWB)       // 10240
#define B_SZ     (BKC * BROWB)       // 8704
#define STAGE_SZ (A_SZ + B_SZ)       // 18944
#define NSTG     4
#define FFN_SMEM (NSTG * STAGE_SZ)   // 75776

__device__ __forceinline__ void ffn_load_chunk(int kc, uint32_t stage, const int* stok,
                                               int e, int h0, int tid) {
    int k0 = kc * BKC;
#pragma unroll
    for (int it = 0; it < 4; it++) {
        int id = tid + it * 256;
        uint32_t dst;
        const __half* src;
        int sz = 16;
        if (id < 512) {             // A: 128 rows x 4 x 16B
            int row = id >> 2, seg = id & 3;
            int t = stok[row];
            src = g_xh + ((size_t)(t < 0 ? 0 : t) * MDIM + k0 + seg * 8);
            if (t < 0) sz = 0;
            dst = stage + row * AROWB + seg * 16;
        } else {                    // B: 32 k-rows x 16 x 16B (native w1 layout)
            int b = id - 512;
            int row = b >> 4, seg = b & 15;
            src = g_w1h + ((size_t)(e * MDIM + k0 + row) * HDIM + h0 + seg * 8);
            dst = stage + A_SZ + row * BROWB + seg * 16;
        }
        CP_ASYNC16(dst, src, sz);
    }
    CP_COMMIT();
}

__global__ __launch_bounds__(256, 2) void ffn_kernel(const float* __restrict__ b1) {
    extern __shared__ __align__(128) char smem[];
    __shared__ int stok[128];

    int h0 = blockIdx.x * 128;
    int e  = blockIdx.y >> 4;
    int c0 = (blockIdx.y & 15) * 128;
    int ne = g_ne[e];
    if (c0 >= ne) return;

    int tid = threadIdx.x, wid = tid >> 5, lane = tid & 31;
    int warpm = wid & 1, warpn = wid >> 1;   // 2 x 4 warp grid -> 64m x 32n per warp
    uint32_t sbase = smem_u32(smem);

    if (tid < 128) {
        int c = c0 + tid;
        stok[tid] = (c < ne) ? g_tok[e * CCAP + c] : -1;
    }
    __syncthreads();

    ffn_load_chunk(0, sbase + 0 * STAGE_SZ, stok, e, h0, tid);
    ffn_load_chunk(1, sbase + 1 * STAGE_SZ, stok, e, h0, tid);
    ffn_load_chunk(2, sbase + 2 * STAGE_SZ, stok, e, h0, tid);

    float acc[4][4][4];
#pragma unroll
    for (int i = 0; i < 4; i++)
#pragma unroll
        for (int j = 0; j < 4; j++)
#pragma unroll
            for (int q = 0; q < 4; q++) acc[i][j][q] = 0.f;

    // per-lane ldmatrix offsets
    uint32_t aOff = (uint32_t)((warpm * 64 + (lane & 15)) * AROWB + ((lane >> 4) & 1) * 16);
    uint32_t bOff = (uint32_t)(A_SZ + ((lane & 7) + ((lane >> 3) & 1) * 8) * BROWB
                               + (warpn * 32 + ((lane >> 4) & 1) * 8) * 2);

    for (int kc = 0; kc < NCH; kc++) {
        CP_WAIT2();
        __syncthreads();
        // issue next tile's loads BEFORE compute: overwrites stage (kc-1)&3,
        // which the barrier above just proved everyone finished reading.
        if (kc + 3 < NCH)
            ffn_load_chunk(kc + 3, sbase + (uint32_t)((kc + 3) & (NSTG - 1)) * STAGE_SZ, stok, e, h0, tid);
        else
            CP_COMMIT();   // keep group count consistent for wait_group 2

        uint32_t stage = sbase + (uint32_t)(kc & (NSTG - 1)) * STAGE_SZ;
#pragma unroll
        for (int ks = 0; ks < 2; ks++) {
            uint32_t ah[4][4], bh[8];
#pragma unroll
            for (int mf = 0; mf < 4; mf++)
                ldsm4(ah[mf], stage + aOff + mf * (16 * AROWB) + ks * 32);
#pragma unroll
            for (int p = 0; p < 2; p++)
                ldsm4t(bh + p * 4, stage + bOff + (uint32_t)(ks * 16) * BROWB + p * 32);
#pragma unroll
            for (int mf = 0; mf < 4; mf++)
#pragma unroll
                for (int nf = 0; nf < 4; nf++)
                    mma16816(acc[mf][nf], ah[mf], bh + nf * 2);
        }
    }

    // epilogue: fuse relu(+b1) . w2sum, reduce n within warp, atomicAdd z
    int hb = h0 + warpn * 32 + (lane & 3) * 2;
    float b1v[4][2], wsv[4][2];
#pragma unroll
    for (int nf = 0; nf < 4; nf++) {
        int hc = hb + nf * 8;
        b1v[nf][0] = b1[e * HDIM + hc];     b1v[nf][1] = b1[e * HDIM + hc + 1];
        wsv[nf][0] = g_w2sum[e * HDIM + hc]; wsv[nf][1] = g_w2sum[e * HDIM + hc + 1];
    }
#pragma unroll
    for (int mf = 0; mf < 4; mf++) {
        float z0 = 0.f, z1 = 0.f;
#pragma unroll
        for (int nf = 0; nf < 4; nf++) {
            float v;
            v = acc[mf][nf][0] + b1v[nf][0]; if (v > 0.f) z0 += v * wsv[nf][0];
            v = acc[mf][nf][1] + b1v[nf][1]; if (v > 0.f) z0 += v * wsv[nf][1];
            v = acc[mf][nf][2] + b1v[nf][0]; if (v > 0.f) z1 += v * wsv[nf][0];
            v = acc[mf][nf][3] + b1v[nf][1]; if (v > 0.f) z1 += v * wsv[nf][1];
        }
        z0 += __shfl_xor_sync(0xffffffffu, z0, 1); z0 += __shfl_xor_sync(0xffffffffu, z0, 2);
        z1 += __shfl_xor_sync(0xffffffffu, z1, 1); z1 += __shfl_xor_sync(0xffffffffu, z1, 2);
        if ((lane & 3) == 0) {
            int r = c0 + warpm * 64 + mf * 16 + (lane >> 2);
            if (r < ne)     atomicAdd(&g_z[e * CCAP + r], z0);
            if (r + 8 < ne) atomicAdd(&g_z[e * CCAP + r + 8], z1);
        }
    }
}

// ---------------- fused combine + per-batch log_softmax ---------------------
__global__ __launch_bounds__(1024) void final_kernel(float* __restrict__ out) {
    int b = blockIdx.x, tid = threadIdx.x;
    int lane = tid & 31, wid = tid >> 5;
    __shared__ float sh[32];

    float v[2];
#pragma unroll
    for (int i = 0; i < 2; i++) {
        int s = b * TT + tid + i * 1024;
        float val = 0.f;
        int p0 = g_pos0[s];
        if (p0 >= 0) { int e = g_e0[s]; val += g_g0[s] * (g_z[e * CCAP + p0] + g_b2sum[e]); }
        int p1 = g_pos1[s];
        if (p1 >= 0) { int e = g_e1[s]; val += g_g1[s] * (g_z[e * CCAP + p1] + g_b2sum[e]); }
        v[i] = val;
    }

    float mx = fmaxf(v[0], v[1]);
#pragma unroll
    for (int o = 16; o; o >>= 1) mx = fmaxf(mx, __shfl_xor_sync(0xffffffffu, mx, o));
    if (lane == 0) sh[wid] = mx;
    __syncthreads();
    if (wid == 0) {
        float m = sh[lane];
#pragma unroll
        for (int o = 16; o; o >>= 1) m = fmaxf(m, __shfl_xor_sync(0xffffffffu, m, o));
        if (lane == 0) sh[0] = m;
    }
    __syncthreads();
    mx = sh[0];
    __syncthreads();

    float sum = expf(v[0] - mx) + expf(v[1] - mx);
#pragma unroll
    for (int o = 16; o; o >>= 1) sum += __shfl_xor_sync(0xffffffffu, sum, o);
    if (lane == 0) sh[wid] = sum;
    __syncthreads();
    if (wid == 0) {
        float m = sh[lane];
#pragma unroll
        for (int o = 16; o; o >>= 1) m += __shfl_xor_sync(0xffffffffu, m, o);
        if (lane == 0) sh[0] = m;
    }
    __syncthreads();
    float lse = logf(sh[0]);

    out[b * TT + tid]        = v[0] - mx - lse;
    out[b * TT + tid + 1024] = v[1] - mx - lse;
}

// ---------------- launch: fork/join stream overlap ---------------------------
extern "C" void kernel_launch(void* const* d_in, const int* in_sizes, int n_in,
                              void* d_out, int out_size) {
    const float* x  = (const float*)d_in[0];
    const float* wg = (const float*)d_in[1];
    const float* w1 = (const float*)d_in[2];
    const float* b1 = (const float*)d_in[3];
    const float* w2 = (const float*)d_in[4];
    const float* b2 = (const float*)d_in[5];
    float* out = (float*)d_out;

    // Side stream + events, created per call (host-side resources only; no
    // device memory). kernel_launch runs twice (correctness + capture); graph
    // replays never re-execute this host code.
    cudaStream_t s2;
    cudaEvent_t eFork, eJoin;
    cudaStreamCreateWithFlags(&s2, cudaStreamNonBlocking);
    cudaEventCreateWithFlags(&eFork, cudaEventDisableTiming);
    cudaEventCreateWithFlags(&eJoin, cudaEventDisableTiming);

    // fork: side stream converts w1 while main stream does routing + scan
    cudaEventRecord(eFork, 0);
    cudaStreamWaitEvent(s2, eFork, 0);
    cvt_w1_kernel<<<EEXP * MDIM * HDIM / 4 / 256, 256, 0, s2>>>(w1);
    cudaEventRecord(eJoin, s2);

    route_w2_kernel<<<3073, 256>>>(x, wg, w2, b2);
    scan_kernel<<<1, 1024>>>();

    // join: ffn needs g_w1h from the side stream
    cudaStreamWaitEvent(0, eJoin, 0);

    cudaFuncSetAttribute(ffn_kernel, cudaFuncAttributeMaxDynamicSharedMemorySize, FFN_SMEM);
    dim3 g(HDIM / 128, EEXP * (CCAP / 128));
    ffn_kernel<<<g, 256, FFN_SMEM>>>(b1);

    final_kernel<<<BB, 1024>>>(out);
}

// round 16
// speedup vs baseline: 1.0303x; 1.0303x over previous
#include <cuda_runtime.h>
#include <cuda_fp16.h>
#include <cstdint>

#define S_TOK 8192
#define MDIM  1024
#define EEXP  8
#define HDIM  2048
#define CCAP  2048
#define BB    4
#define TT    2048

// ---------------- scratch (device globals; no allocations allowed) ----------
__device__ int   g_e0[S_TOK], g_e1[S_TOK];
__device__ float g_g0[S_TOK], g_g1[S_TOK];
__device__ int   g_pos0[S_TOK], g_pos1[S_TOK];
__device__ int   g_tok[EEXP * CCAP];
__device__ int   g_ne[EEXP];
__device__ float g_w2sum[EEXP * HDIM];
__device__ float g_b2sum[EEXP];
__device__ float g_z[EEXP * CCAP];
// fp16 operands (single-term, 11-bit mantissa)
__device__ __half g_xh[S_TOK * MDIM];
__device__ __half g_w1h[EEXP * MDIM * HDIM];   // native layout [e][m][h]

// ---------------- PTX helpers (family-portable only) -------------------------
__device__ __forceinline__ uint32_t smem_u32(const void* p) {
    uint32_t a;
    asm("{ .reg .u64 t; cvta.to.shared.u64 t, %1; cvt.u32.u64 %0, t; }" : "=r"(a) : "l"(p));
    return a;
}
__device__ __forceinline__ void ldsm4(uint32_t* r, uint32_t addr) {
    asm volatile("ldmatrix.sync.aligned.m8n8.x4.shared.b16 {%0,%1,%2,%3}, [%4];"
                 : "=r"(r[0]), "=r"(r[1]), "=r"(r[2]), "=r"(r[3]) : "r"(addr));
}
__device__ __forceinline__ void ldsm4t(uint32_t* r, uint32_t addr) {
    asm volatile("ldmatrix.sync.aligned.m8n8.x4.trans.shared.b16 {%0,%1,%2,%3}, [%4];"
                 : "=r"(r[0]), "=r"(r[1]), "=r"(r[2]), "=r"(r[3]) : "r"(addr));
}
__device__ __forceinline__ void mma16816(float* c, const uint32_t* a, const uint32_t* b) {
    asm volatile("mma.sync.aligned.m16n8k16.row.col.f32.f16.f16.f32 "
                 "{%0,%1,%2,%3}, {%4,%5,%6,%7}, {%8,%9}, {%0,%1,%2,%3};"
                 : "+f"(c[0]), "+f"(c[1]), "+f"(c[2]), "+f"(c[3])
                 : "r"(a[0]), "r"(a[1]), "r"(a[2]), "r"(a[3]), "r"(b[0]), "r"(b[1]));
}
#define CP_ASYNC16(dst, src, sz) \
    asm volatile("cp.async.cg.shared.global [%0], [%1], 16, %2;" :: "r"(dst), "l"(src), "r"(sz) : "memory")
#define CP_COMMIT() asm volatile("cp.async.commit_group;" ::: "memory")
#define CP_WAIT2()  asm volatile("cp.async.wait_group 2;" ::: "memory")

// ---------------- fused routing + prep ---------------------------------------
// blocks [0,1024): routing (warp per token + x->fp16)
// blocks [1024,17408): w1 -> fp16
// blocks [17408,19456): w2 row-sum
// block  19456: b2 row-sum
__global__ __launch_bounds__(256) void route_prep_kernel(const float* __restrict__ x,
                                                         const float* __restrict__ wg,
                                                         const float* __restrict__ w1,
                                                         const float* __restrict__ w2,
                                                         const float* __restrict__ b2) {
    int bx = blockIdx.x;
    int lane = threadIdx.x & 31;
    if (bx < 1024) {
        // ---- routing ----
        int gwarp = (bx * 256 + threadIdx.x) >> 5;
        const float* xr = x + (size_t)gwarp * MDIM;
        __half* xo = g_xh + (size_t)gwarp * MDIM;
        float acc[8];
#pragma unroll
        for (int e = 0; e < 8; e++) acc[e] = 0.f;
        for (int k = lane; k < MDIM; k += 32) {
            float xv = xr[k];
            xo[k] = __float2half(xv);
            const float4* w4 = (const float4*)(wg + (size_t)k * EEXP);
            float4 a = w4[0], b = w4[1];
            acc[0] += xv * a.x; acc[1] += xv * a.y; acc[2] += xv * a.z; acc[3] += xv * a.w;
            acc[4] += xv * b.x; acc[5] += xv * b.y; acc[6] += xv * b.z; acc[7] += xv * b.w;
        }
#pragma unroll
        for (int e = 0; e < 8; e++) {
#pragma unroll
            for (int o = 16; o; o >>= 1) acc[e] += __shfl_xor_sync(0xffffffffu, acc[e], o);
        }
        if (lane == 0) {
            float mx = acc[0];
#pragma unroll
            for (int e = 1; e < 8; e++) mx = fmaxf(mx, acc[e]);
            float p[8]; float den = 0.f;
#pragma unroll
            for (int e = 0; e < 8; e++) { p[e] = expf(acc[e] - mx); den += p[e]; }
#pragma unroll
            for (int e = 0; e < 8; e++) p[e] /= den;
            int i0 = 0; float v0 = p[0];
#pragma unroll
            for (int e = 1; e < 8; e++) if (p[e] > v0) { v0 = p[e]; i0 = e; }
            int i1 = -1; float v1 = -1.f;
#pragma unroll
            for (int e = 0; e < 8; e++) if (e != i0 && p[e] > v1) { v1 = p[e]; i1 = e; }
            float gden = v0 + v1 + 1e-9f;
            g_e0[gwarp] = i0;  g_e1[gwarp] = i1;
            g_g0[gwarp] = v0 / gden;  g_g1[gwarp] = v1 / gden;
        }
        return;
    }
    if (bx < 17408) {
        // ---- w1 -> fp16 ----
        int i = (bx - 1024) * 256 + threadIdx.x;
        float4 v = ((const float4*)w1)[i];
        __half2* o = (__half2*)g_w1h;
        o[2*i]   = __floats2half2_rn(v.x, v.y);
        o[2*i+1] = __floats2half2_rn(v.z, v.w);
        return;
    }
    if (bx < 19456) {
        // ---- w2 row-sum ----
        int row = ((bx - 17408) * 256 + threadIdx.x) >> 5;
        const float4* p = (const float4*)(w2 + (size_t)row * MDIM);
        float s = 0.f;
#pragma unroll
        for (int i = 0; i < 8; i++) {
            float4 v = p[lane + i * 32];
            s += (v.x + v.y) + (v.z + v.w);
        }
#pragma unroll
        for (int o = 16; o; o >>= 1) s += __shfl_xor_sync(0xffffffffu, s, o);
        if (lane == 0) g_w2sum[row] = s;
        return;
    }
    // ---- b2 row-sum ----
    int warp = threadIdx.x >> 5;
    if (warp < EEXP) {
        float s = 0.f;
        for (int m = lane; m < MDIM; m += 32) s += b2[warp * MDIM + m];
#pragma unroll
        for (int o = 16; o; o >>= 1) s += __shfl_xor_sync(0xffffffffu, s, o);
        if (lane == 0) g_b2sum[warp] = s;
    }
}

// ---------------- ordered rank / capacity scan: single pass prefix ----------
// Each thread owns 8 consecutive tokens. 16 categories (j*8+e) packed as
// 16-bit fields in 4x u64. Position = warp-base (shared) + thread-exclusive
// prefix (register select) + earlier-same-cat count (register compares).
// No local-memory indexed arrays. Also zeroes g_z (fused).
__device__ __forceinline__ unsigned long long sel4(const unsigned long long* v, int q) {
    unsigned long long lo = (q & 1) ? v[1] : v[0];
    unsigned long long hi = (q & 1) ? v[3] : v[2];
    return (q & 2) ? hi : lo;
}

__global__ __launch_bounds__(1024) void scan_kernel() {
    __shared__ unsigned long long wtot[32][4];
    __shared__ unsigned long long wbase[32][4];
    __shared__ unsigned long long gtot[4];
    int tid = threadIdx.x, lane = tid & 31, warp = tid >> 5;

    int e0v[8], e1v[8];
    unsigned long long c[4] = {0ull, 0ull, 0ull, 0ull};
#pragma unroll
    for (int i = 0; i < 8; i++) {
        int s = tid * 8 + i;
        int e0 = g_e0[s], e1 = g_e1[s];
        e0v[i] = e0; e1v[i] = e1;
        if (e0 < 4) c[0] += 1ull << (e0 * 16); else c[1] += 1ull << ((e0 - 4) * 16);
        if (e1 < 4) c[2] += 1ull << (e1 * 16); else c[3] += 1ull << ((e1 - 4) * 16);
    }
    unsigned long long inc[4] = {c[0], c[1], c[2], c[3]};
#pragma unroll
    for (int st = 1; st < 32; st <<= 1) {
#pragma unroll
        for (int q = 0; q < 4; q++) {
            unsigned long long o = __shfl_up_sync(0xffffffffu, inc[q], st);
            if (lane >= st) inc[q] += o;
        }
    }
    if (lane == 31) {
#pragma unroll
        for (int q = 0; q < 4; q++) wtot[warp][q] = inc[q];
    }
    __syncthreads();
    if (warp == 0) {
        unsigned long long t[4], ti[4];
#pragma unroll
        for (int q = 0; q < 4; q++) { t[q] = wtot[lane][q]; ti[q] = t[q]; }
#pragma unroll
        for (int st = 1; st < 32; st <<= 1) {
#pragma unroll
            for (int q = 0; q < 4; q++) {
                unsigned long long o = __shfl_up_sync(0xffffffffu, ti[q], st);
                if (lane >= st) ti[q] += o;
            }
        }
#pragma unroll
        for (int q = 0; q < 4; q++) wbase[lane][q] = ti[q] - t[q];
        if (lane == 31) {
#pragma unroll
            for (int q = 0; q < 4; q++) gtot[q] = ti[q];
        }
    }
    __syncthreads();

    // thread-exclusive packed prefix
    unsigned long long excl[4];
#pragma unroll
    for (int q = 0; q < 4; q++) excl[q] = inc[q] - c[q];

#pragma unroll
    for (int i = 0; i < 8; i++) {
        int s = tid * 8 + i;
        // j = 0 stream: cat = e0, packed group q = e>>2, field r = e&3
        {
            int e = e0v[i];
            int q = e >> 2, sh = (e & 3) * 16;
            int base = (int)((wbase[warp][q] >> sh) & 0xffff)
                     + (int)((sel4(excl, q) >> sh) & 0xffff);
            int m = 0;
#pragma unroll
            for (int j = 0; j < 8; j++) if (j < i) m += (e0v[j] == e);
            int p0 = base + m;
            if (p0 < CCAP) { g_pos0[s] = p0; g_tok[e * CCAP + p0] = s; } else g_pos0[s] = -1;
        }
        // j = 1 stream: packed group q+2, plus global j=0 totals offset
        {
            int e = e1v[i];
            int q = e >> 2, sh = (e & 3) * 16;
            int base = (int)((wbase[warp][q + 2] >> sh) & 0xffff)
                     + (int)((sel4(excl, q + 2) >> sh) & 0xffff)
                     + (int)((gtot[q] >> sh) & 0xffff);
            int m = 0;
#pragma unroll
            for (int j = 0; j < 8; j++) if (j < i) m += (e1v[j] == e);
            int p1 = base + m;
            if (p1 < CCAP) { g_pos1[s] = p1; g_tok[e * CCAP + p1] = s; } else g_pos1[s] = -1;
        }
    }
    // fused: zero z accumulators + expert counts
#pragma unroll
    for (int i = 0; i < EEXP * CCAP / 1024; i++) g_z[tid + i * 1024] = 0.f;
    if (tid < EEXP) {
        int q = tid >> 2, r = tid & 3;
        int tot = (int)((gtot[q] >> (r * 16)) & 0xffff) + (int)((gtot[q + 2] >> (r * 16)) & 0xffff);
        g_ne[tid] = min(tot, CCAP);
    }
}

// ---------------- FFN via mma.sync fp16 (single term) ------------------------
// CTA tile: 128 tok x 128 H, BK = 32, 4-stage cp.async pipeline, 2 CTAs/SM.
// One __syncthreads per chunk; next tile's loads issued BEFORE compute so
// cp.async overlaps the MMAs. (Exact config of the 268.6/260.8 us runs — FROZEN.)
#define BKC      32
#define NCH      (MDIM / BKC)        // 32
#define AROWB    80
#define BROWB    272
#define A_SZ     (128 * AROWB)       // 10240
#define B_SZ     (BKC * BROWB)       // 8704
#define STAGE_SZ (A_SZ + B_SZ)       // 18944
#define NSTG     4
#define FFN_SMEM (NSTG * STAGE_SZ)   // 75776

__device__ __forceinline__ void ffn_load_chunk(int kc, uint32_t stage, const int* stok,
                                               int e, int h0, int tid) {
    int k0 = kc * BKC;
#pragma unroll
    for (int it = 0; it < 4; it++) {
        int id = tid + it * 256;
        uint32_t dst;
        const __half* src;
        int sz = 16;
        if (id < 512) {             // A: 128 rows x 4 x 16B
            int row = id >> 2, seg = id & 3;
            int t = stok[row];
            src = g_xh + ((size_t)(t < 0 ? 0 : t) * MDIM + k0 + seg * 8);
            if (t < 0) sz = 0;
            dst = stage + row * AROWB + seg * 16;
        } else {                    // B: 32 k-rows x 16 x 16B (native w1 layout)
            int b = id - 512;
            int row = b >> 4, seg = b & 15;
            src = g_w1h + ((size_t)(e * MDIM + k0 + row) * HDIM + h0 + seg * 8);
            dst = stage + A_SZ + row * BROWB + seg * 16;
        }
        CP_ASYNC16(dst, src, sz);
    }
    CP_COMMIT();
}

__global__ __launch_bounds__(256, 2) void ffn_kernel(const float* __restrict__ b1) {
    extern __shared__ __align__(128) char smem[];
    __shared__ int stok[128];

    int h0 = blockIdx.x * 128;
    int e  = blockIdx.y >> 4;
    int c0 = (blockIdx.y & 15) * 128;
    int ne = g_ne[e];
    if (c0 >= ne) return;

    int tid = threadIdx.x, wid = tid >> 5, lane = tid & 31;
    int warpm = wid & 1, warpn = wid >> 1;   // 2 x 4 warp grid -> 64m x 32n per warp
    uint32_t sbase = smem_u32(smem);

    if (tid < 128) {
        int c = c0 + tid;
        stok[tid] = (c < ne) ? g_tok[e * CCAP + c] : -1;
    }
    __syncthreads();

    ffn_load_chunk(0, sbase + 0 * STAGE_SZ, stok, e, h0, tid);
    ffn_load_chunk(1, sbase + 1 * STAGE_SZ, stok, e, h0, tid);
    ffn_load_chunk(2, sbase + 2 * STAGE_SZ, stok, e, h0, tid);

    float acc[4][4][4];
#pragma unroll
    for (int i = 0; i < 4; i++)
#pragma unroll
        for (int j = 0; j < 4; j++)
#pragma unroll
            for (int q = 0; q < 4; q++) acc[i][j][q] = 0.f;

    // per-lane ldmatrix offsets
    uint32_t aOff = (uint32_t)((warpm * 64 + (lane & 15)) * AROWB + ((lane >> 4) & 1) * 16);
    uint32_t bOff = (uint32_t)(A_SZ + ((lane & 7) + ((lane >> 3) & 1) * 8) * BROWB
                               + (warpn * 32 + ((lane >> 4) & 1) * 8) * 2);

    for (int kc = 0; kc < NCH; kc++) {
        CP_WAIT2();
        __syncthreads();
        // issue next tile's loads BEFORE compute: overwrites stage (kc-1)&3,
        // which the barrier above just proved everyone finished reading.
        if (kc + 3 < NCH)
            ffn_load_chunk(kc + 3, sbase + (uint32_t)((kc + 3) & (NSTG - 1)) * STAGE_SZ, stok, e, h0, tid);
        else
            CP_COMMIT();   // keep group count consistent for wait_group 2

        uint32_t stage = sbase + (uint32_t)(kc & (NSTG - 1)) * STAGE_SZ;
#pragma unroll
        for (int ks = 0; ks < 2; ks++) {
            uint32_t ah[4][4], bh[8];
#pragma unroll
            for (int mf = 0; mf < 4; mf++)
                ldsm4(ah[mf], stage + aOff + mf * (16 * AROWB) + ks * 32);
#pragma unroll
            for (int p = 0; p < 2; p++)
                ldsm4t(bh + p * 4, stage + bOff + (uint32_t)(ks * 16) * BROWB + p * 32);
#pragma unroll
            for (int mf = 0; mf < 4; mf++)
#pragma unroll
                for (int nf = 0; nf < 4; nf++)
                    mma16816(acc[mf][nf], ah[mf], bh + nf * 2);
        }
    }

    // epilogue: fuse relu(+b1) . w2sum, reduce n within warp, atomicAdd z
    int hb = h0 + warpn * 32 + (lane & 3) * 2;
    float b1v[4][2], wsv[4][2];
#pragma unroll
    for (int nf = 0; nf < 4; nf++) {
        int hc = hb + nf * 8;
        b1v[nf][0] = b1[e * HDIM + hc];     b1v[nf][1] = b1[e * HDIM + hc + 1];
        wsv[nf][0] = g_w2sum[e * HDIM + hc]; wsv[nf][1] = g_w2sum[e * HDIM + hc + 1];
    }
#pragma unroll
    for (int mf = 0; mf < 4; mf++) {
        float z0 = 0.f, z1 = 0.f;
#pragma unroll
        for (int nf = 0; nf < 4; nf++) {
            float v;
            v = acc[mf][nf][0] + b1v[nf][0]; if (v > 0.f) z0 += v * wsv[nf][0];
            v = acc[mf][nf][1] + b1v[nf][1]; if (v > 0.f) z0 += v * wsv[nf][1];
            v = acc[mf][nf][2] + b1v[nf][0]; if (v > 0.f) z1 += v * wsv[nf][0];
            v = acc[mf][nf][3] + b1v[nf][1]; if (v > 0.f) z1 += v * wsv[nf][1];
        }
        z0 += __shfl_xor_sync(0xffffffffu, z0, 1); z0 += __shfl_xor_sync(0xffffffffu, z0, 2);
        z1 += __shfl_xor_sync(0xffffffffu, z1, 1); z1 += __shfl_xor_sync(0xffffffffu, z1, 2);
        if ((lane & 3) == 0) {
            int r = c0 + warpm * 64 + mf * 16 + (lane >> 2);
            if (r < ne)     atomicAdd(&g_z[e * CCAP + r], z0);
            if (r + 8 < ne) atomicAdd(&g_z[e * CCAP + r + 8], z1);
        }
    }
}

// ---------------- fused combine + per-batch log_softmax ---------------------
__global__ __launch_bounds__(1024) void final_kernel(float* __restrict__ out) {
    int b = blockIdx.x, tid = threadIdx.x;
    int lane = tid & 31, wid = tid >> 5;
    __shared__ float sh[32];

    float v[2];
#pragma unroll
    for (int i = 0; i < 2; i++) {
        int s = b * TT + tid + i * 1024;
        float val = 0.f;
        int p0 = g_pos0[s];
        if (p0 >= 0) { int e = g_e0[s]; val += g_g0[s] * (g_z[e * CCAP + p0] + g_b2sum[e]); }
        int p1 = g_pos1[s];
        if (p1 >= 0) { int e = g_e1[s]; val += g_g1[s] * (g_z[e * CCAP + p1] + g_b2sum[e]); }
        v[i] = val;
    }

    float mx = fmaxf(v[0], v[1]);
#pragma unroll
    for (int o = 16; o; o >>= 1) mx = fmaxf(mx, __shfl_xor_sync(0xffffffffu, mx, o));
    if (lane == 0) sh[wid] = mx;
    __syncthreads();
    if (wid == 0) {
        float m = sh[lane];
#pragma unroll
        for (int o = 16; o; o >>= 1) m = fmaxf(m, __shfl_xor_sync(0xffffffffu, m, o));
        if (lane == 0) sh[0] = m;
    }
    __syncthreads();
    mx = sh[0];
    __syncthreads();

    float sum = expf(v[0] - mx) + expf(v[1] - mx);
#pragma unroll
    for (int o = 16; o; o >>= 1) sum += __shfl_xor_sync(0xffffffffu, sum, o);
    if (lane == 0) sh[wid] = sum;
    __syncthreads();
    if (wid == 0) {
        float m = sh[lane];
#pragma unroll
        for (int o = 16; o; o >>= 1) m += __shfl_xor_sync(0xffffffffu, m, o);
        if (lane == 0) sh[0] = m;
    }
    __syncthreads();
    float lse = logf(sh[0]);

    out[b * TT + tid]        = v[0] - mx - lse;
    out[b * TT + tid + 1024] = v[1] - mx - lse;
}

// ---------------- launch -----------------------------------------------------
extern "C" void kernel_launch(void* const* d_in, const int* in_sizes, int n_in,
                              void* d_out, int out_size) {
    const float* x  = (const float*)d_in[0];
    const float* wg = (const float*)d_in[1];
    const float* w1 = (const float*)d_in[2];
    const float* b1 = (const float*)d_in[3];
    const float* w2 = (const float*)d_in[4];
    const float* b2 = (const float*)d_in[5];
    float* out = (float*)d_out;

    route_prep_kernel<<<19457, 256>>>(x, wg, w1, w2, b2);
    scan_kernel<<<1, 1024>>>();

    cudaFuncSetAttribute(ffn_kernel, cudaFuncAttributeMaxDynamicSharedMemorySize, FFN_SMEM);
    dim3 g(HDIM / 128, EEXP * (CCAP / 128));
    ffn_kernel<<<g, 256, FFN_SMEM>>>(b1);

    final_kernel<<<BB, 1024>>>(out);
}